// round 2
// baseline (speedup 1.0000x reference)
#include <cuda_runtime.h>
#include <cstdint>

// ============================================================================
// VersatileConvSE3: out[e,o,s] = sum_{c,f} rw[e,o,c*44+f] * T_f[e,c,s]
//   rw[e,o,cf] = sum_m h[e,m] * w3[o*1408+cf, m]      (h from small MLP)
//   T_f[e,c,s] = sum_d feat[e,c,d] * basis[e,d,f,s]
// E=16384, C=32, O=32, D=S=16, F=44, M=32, cf = c*44+f (1408)
// ============================================================================

#define E_TOT   16384
#define NEPB    8          // edges per CTA
#define NBLK    (E_TOT / NEPB)

typedef unsigned long long u64;

#define FMA2(d,a,b,c) asm("fma.rn.f32x2 %0, %1, %2, %3;" : "=l"(d) : "l"(a), "l"(b), "l"(c))

__device__ __forceinline__ u64 pk2(float a, float b) {
    u64 r; asm("mov.b64 %0, {%1, %2};" : "=l"(r) : "f"(a), "f"(b)); return r;
}
__device__ __forceinline__ float2 upk2(u64 v) {
    float a, b; asm("mov.b64 {%0, %1}, %2;" : "=f"(a), "=f"(b) : "l"(v));
    return make_float2(a, b);
}

__device__ float g_H[E_TOT * 32];   // MLP output h[e][m]

// ---------------------------------------------------------------------------
// Kernel 1: radial MLP -> g_H.  One warp per edge.
// ---------------------------------------------------------------------------
__device__ __forceinline__ float warp_sum(float v) {
    v += __shfl_xor_sync(0xffffffffu, v, 16);
    v += __shfl_xor_sync(0xffffffffu, v, 8);
    v += __shfl_xor_sync(0xffffffffu, v, 4);
    v += __shfl_xor_sync(0xffffffffu, v, 2);
    v += __shfl_xor_sync(0xffffffffu, v, 1);
    return v;
}

__global__ __launch_bounds__(256) void mlp_kernel(
    const float* __restrict__ inv,
    const float* __restrict__ w1, const float* __restrict__ b1,
    const float* __restrict__ g1, const float* __restrict__ be1,
    const float* __restrict__ w2, const float* __restrict__ b2,
    const float* __restrict__ g2, const float* __restrict__ be2)
{
    const int e    = blockIdx.x * 8 + (threadIdx.x >> 5);
    const int lane = threadIdx.x & 31;
    const float* x = inv + e * 16;

    float y = b1[lane];
    #pragma unroll
    for (int d = 0; d < 16; ++d) y += x[d] * w1[lane * 16 + d];

    float mu  = warp_sum(y) * (1.0f / 32.0f);
    float dz  = y - mu;
    float var = warp_sum(dz * dz) * (1.0f / 32.0f);
    float rs  = rsqrtf(var + 1e-5f);
    float h1  = fmaxf(dz * rs * g1[lane] + be1[lane], 0.0f);

    float y2 = b2[lane];
    #pragma unroll
    for (int m = 0; m < 32; ++m)
        y2 += __shfl_sync(0xffffffffu, h1, m) * w2[lane * 32 + m];

    mu  = warp_sum(y2) * (1.0f / 32.0f);
    dz  = y2 - mu;
    var = warp_sum(dz * dz) * (1.0f / 32.0f);
    rs  = rsqrtf(var + 1e-5f);
    g_H[e * 32 + lane] = fmaxf(dz * rs * g2[lane] + be2[lane], 0.0f);
}

// ---------------------------------------------------------------------------
// Kernel 2: fused conv.  8 edges per CTA, 256 threads.
// warp w owns o in [4w, 4w+4); lane = e*4 + osub  (e = lane>>2).
// Per f: stage basis slice, build T in smem; loop c-chunks of 4, staging
// w3 rows [32o x 32m] per c in smem, reused by all 8 edges.
// All inner products use packed fma.rn.f32x2.
// ---------------------------------------------------------------------------
// smem layout (floats):
#define OF_FEAT 0            // [8][32][20]  = 5120  (padded rows)
#define OF_BAS  5120         // [8][16][16]  = 2048
#define OF_T    7168         // [32][132]    = 4224  (c-major, [c][e][16], pad 132)
#define OF_W3   11392        // [4][32][36]  = 4608  (cj-major, padded rows)
#define OF_H    16000        // [8][32]      = 256
#define SMEM_FLOATS 16256    // 65024 bytes

__global__ __launch_bounds__(256, 2) void conv_kernel(
    const float* __restrict__ feat,
    const float* __restrict__ basis,
    const float* __restrict__ w3,
    float* __restrict__ out)
{
    extern __shared__ __align__(16) float sm[];
    float* sFeat = sm + OF_FEAT;
    float* sBas  = sm + OF_BAS;
    float* sT    = sm + OF_T;
    float* sW3   = sm + OF_W3;
    float* sH    = sm + OF_H;

    const int tid  = threadIdx.x;
    const int e0   = blockIdx.x * NEPB;
    const int lane = tid & 31;
    const int warp = tid >> 5;
    const int my_e = lane >> 2;
    const int my_o = (warp << 2) + (lane & 3);

    // ---- load feat tile: thread t -> (e = t>>5, c = t&31), 16 floats ----
    {
        const int e = tid >> 5, c = tid & 31;
        const float4* src = (const float4*)(feat + ((size_t)(e0 + e) * 32 + c) * 16);
        float4* dst = (float4*)(sFeat + e * 640 + c * 20);
        #pragma unroll
        for (int i = 0; i < 4; ++i) dst[i] = src[i];
    }
    sH[tid] = g_H[e0 * 32 + tid];   // 8*32 == 256

    // ---- basis prefetch ids: thread t -> (row = t>>1 : e,d ; half = t&1) ----
    const int be = (tid >> 1) >> 4, bd = (tid >> 1) & 15, bh = tid & 1;
    float4 breg[2];
    {
        const float* bs = basis + ((((size_t)(e0 + be) * 16 + bd) * 44 + 0) * 16) + bh * 8;
        breg[0] = __ldg((const float4*)bs);
        breg[1] = __ldg((const float4*)bs + 1);
    }
    // ---- w3 loader ids: thread t -> (row = t>>1 : o,cj ; half = t&1) ----
    const int wo = (tid >> 1) >> 2, wc = (tid >> 1) & 3, wh = tid & 1;
    float4 wreg[4];

    __syncthreads();

    // pack h for my edge into f32x2 registers
    u64 h2[16];
    #pragma unroll
    for (int k = 0; k < 16; ++k)
        h2[k] = pk2(sH[my_e * 32 + 2 * k], sH[my_e * 32 + 2 * k + 1]);

    u64 acc[8];
    #pragma unroll
    for (int k = 0; k < 8; ++k) acc[k] = 0ull;

    for (int f = 0; f < 44; ++f) {
        // stage basis slice for this f
        {
            float4* bp = (float4*)(sBas + be * 256 + bd * 16 + bh * 8);
            bp[0] = breg[0]; bp[1] = breg[1];
        }
        __syncthreads();
        // prefetch basis for f+1 (overlaps T-gen + chunk loop)
        if (f < 43) {
            const float* bs = basis + ((((size_t)(e0 + be) * 16 + bd) * 44 + (f + 1)) * 16) + bh * 8;
            breg[0] = __ldg((const float4*)bs);
            breg[1] = __ldg((const float4*)bs + 1);
        }
        // prefetch w3 chunk 0 of this f
        {
            const float* ws = w3 + ((size_t)wo * 1408 + wc * 44 + f) * 32 + wh * 16;
            #pragma unroll
            for (int i = 0; i < 4; ++i) wreg[i] = __ldg((const float4*)ws + i);
        }

        // ---- T-gen: thread (e = t>>5, c = t&31): T[e,c,s] = sum_d feat*bas ----
        {
            const int e = tid >> 5, c = tid & 31;
            float fr[16];
            #pragma unroll
            for (int i = 0; i < 4; ++i) {
                float4 v = ((const float4*)(sFeat + e * 640 + c * 20))[i];
                fr[4*i] = v.x; fr[4*i+1] = v.y; fr[4*i+2] = v.z; fr[4*i+3] = v.w;
            }
            u64 t[8];
            #pragma unroll
            for (int k = 0; k < 8; ++k) t[k] = 0ull;
            #pragma unroll
            for (int d = 0; d < 16; ++d) {
                u64 fp = pk2(fr[d], fr[d]);
                const u64* brow = (const u64*)(sBas + e * 256 + d * 16);
                #pragma unroll
                for (int i = 0; i < 8; ++i) FMA2(t[i], fp, brow[i], t[i]);
            }
            u64* trow = (u64*)(sT + c * 132 + e * 16);
            #pragma unroll
            for (int i = 0; i < 8; ++i) trow[i] = t[i];
        }
        __syncthreads();

        // ---- c-chunk loop: 8 chunks x 4 c ----
        for (int ch = 0; ch < 8; ++ch) {
            {   // stage current chunk from regs
                float4* wd = (float4*)(sW3 + wc * 1152 + wo * 36 + wh * 16);
                #pragma unroll
                for (int i = 0; i < 4; ++i) wd[i] = wreg[i];
            }
            __syncthreads();
            if (ch < 7) {   // prefetch next chunk (hidden behind compute)
                const float* ws = w3 + ((size_t)wo * 1408 + ((ch + 1) * 4 + wc) * 44 + f) * 32 + wh * 16;
                #pragma unroll
                for (int i = 0; i < 4; ++i) wreg[i] = __ldg((const float4*)ws + i);
            }
            #pragma unroll
            for (int cj = 0; cj < 4; ++cj) {
                const int c = ch * 4 + cj;
                // rw = <h[e,:], w3[o, c*44+f, :]>  (two independent f32x2 chains)
                const u64* wrow = (const u64*)(sW3 + cj * 1152 + my_o * 36);
                u64 ra = 0ull, rb = 0ull;
                #pragma unroll
                for (int m4 = 0; m4 < 8; ++m4) {
                    FMA2(ra, h2[2*m4],     wrow[2*m4],     ra);
                    FMA2(rb, h2[2*m4 + 1], wrow[2*m4 + 1], rb);
                }
                float2 va = upk2(ra), vb = upk2(rb);
                float rw = (va.x + va.y) + (vb.x + vb.y);
                u64 rwp = pk2(rw, rw);
                // acc[s-pair] += rw * T[e,c,s-pair]
                const u64* trow = (const u64*)(sT + c * 132 + my_e * 16);
                #pragma unroll
                for (int i = 0; i < 8; ++i) FMA2(acc[i], rwp, trow[i], acc[i]);
            }
            __syncthreads();
        }
    }

    // ---- store: lane (my_e, my_o) owns out[e0+my_e, my_o, 0..15] ----
    float* op = out + (((size_t)(e0 + my_e) * 32) + my_o) * 16;
    #pragma unroll
    for (int i = 0; i < 4; ++i) {
        ulonglong2 v; v.x = acc[2*i]; v.y = acc[2*i + 1];
        ((ulonglong2*)op)[i] = v;
    }
}

// ---------------------------------------------------------------------------
extern "C" void kernel_launch(void* const* d_in, const int* in_sizes, int n_in,
                              void* d_out, int out_size)
{
    const float* features = (const float*)d_in[0];
    const float* inv      = (const float*)d_in[1];
    const float* basis    = (const float*)d_in[2];
    const float* w1  = (const float*)d_in[3];
    const float* b1  = (const float*)d_in[4];
    const float* g1  = (const float*)d_in[5];
    const float* be1 = (const float*)d_in[6];
    const float* w2  = (const float*)d_in[7];
    const float* b2  = (const float*)d_in[8];
    const float* g2  = (const float*)d_in[9];
    const float* be2 = (const float*)d_in[10];
    const float* w3  = (const float*)d_in[11];
    float* out = (float*)d_out;

    cudaFuncSetAttribute(conv_kernel, cudaFuncAttributeMaxDynamicSharedMemorySize,
                         SMEM_FLOATS * (int)sizeof(float));

    mlp_kernel<<<E_TOT / 8, 256>>>(inv, w1, b1, g1, be1, w2, b2, g2, be2);
    conv_kernel<<<NBLK, 256, SMEM_FLOATS * sizeof(float)>>>(features, basis, w3, out);
}

// round 3
// speedup vs baseline: 1.9318x; 1.9318x over previous
#include <cuda_runtime.h>
#include <cstdint>

// ============================================================================
// VersatileConvSE3: out[e,o,s] = sum_{c,f} rw[e,o,c*44+f] * T_f[e,c,s]
//   rw[e,o,cf] = sum_m h[e,m] * w3[o*1408 + c*44 + f, m]
//   T_f[e,c,s] = sum_d feat[e,c,d] * basis[e,d,f,s]
// E=16384, C=32, O=32, D=S=16, F=44, M=32
// ============================================================================

#define E_TOT   16384
#define NE      16          // edges per CTA
#define NTHR    512
#define NBLK    (E_TOT / NE)

typedef unsigned long long u64;

#define FMA2(d,a,b,c) asm("fma.rn.f32x2 %0, %1, %2, %3;" : "=l"(d) : "l"(a), "l"(b), "l"(c))
#define ADD2(d,a,b)   asm("add.rn.f32x2 %0, %1, %2;"     : "=l"(d) : "l"(a), "l"(b))

__device__ __forceinline__ u64 pk2(float a, float b) {
    u64 r; asm("mov.b64 %0, {%1, %2};" : "=l"(r) : "f"(a), "f"(b)); return r;
}

__device__ float g_H[E_TOT * 32];

// ---------------------------------------------------------------------------
// Kernel 1: radial MLP -> g_H.  One warp per edge.
// ---------------------------------------------------------------------------
__device__ __forceinline__ float warp_sum(float v) {
    v += __shfl_xor_sync(0xffffffffu, v, 16);
    v += __shfl_xor_sync(0xffffffffu, v, 8);
    v += __shfl_xor_sync(0xffffffffu, v, 4);
    v += __shfl_xor_sync(0xffffffffu, v, 2);
    v += __shfl_xor_sync(0xffffffffu, v, 1);
    return v;
}

__global__ __launch_bounds__(256) void mlp_kernel(
    const float* __restrict__ inv,
    const float* __restrict__ w1, const float* __restrict__ b1,
    const float* __restrict__ g1, const float* __restrict__ be1,
    const float* __restrict__ w2, const float* __restrict__ b2,
    const float* __restrict__ g2, const float* __restrict__ be2)
{
    const int e    = blockIdx.x * 8 + (threadIdx.x >> 5);
    const int lane = threadIdx.x & 31;
    const float* x = inv + e * 16;

    float y = b1[lane];
    #pragma unroll
    for (int d = 0; d < 16; ++d) y += x[d] * w1[lane * 16 + d];

    float mu  = warp_sum(y) * (1.0f / 32.0f);
    float dz  = y - mu;
    float var = warp_sum(dz * dz) * (1.0f / 32.0f);
    float rs  = rsqrtf(var + 1e-5f);
    float h1  = fmaxf(dz * rs * g1[lane] + be1[lane], 0.0f);

    float y2 = b2[lane];
    #pragma unroll
    for (int m = 0; m < 32; ++m)
        y2 += __shfl_sync(0xffffffffu, h1, m) * w2[lane * 32 + m];

    mu  = warp_sum(y2) * (1.0f / 32.0f);
    dz  = y2 - mu;
    var = warp_sum(dz * dz) * (1.0f / 32.0f);
    rs  = rsqrtf(var + 1e-5f);
    g_H[e * 32 + lane] = fmaxf(dz * rs * g2[lane] + be2[lane], 0.0f);
}

// ---------------------------------------------------------------------------
// Kernel 2: fused conv. 16 edges per CTA, 512 threads.
// Per f:
//   T-gen : thread (e=tid>>5, c=tid&31) builds T[c][e][16s] (bas broadcast LDS)
//   PhaseA: thread (o=tid>>4, c0=2*(tid&15)) computes rw[o][c0..c0+1][16e]
//           w3 -> registers (LDG, single consumer), h -> broadcast LDS.128
//   PhaseB: thread (cq=tid>>8, og=(tid>>4)&15, e=tid&15) accumulates
//           out[e][2o][16s] over its c-half (persistent registers, reduce at end)
// ---------------------------------------------------------------------------
// smem float offsets (all 16B aligned)
#define OF_H    0                         // [m32][e16]              = 512
#define OF_BAS  512                       // [e16][d16][s16]         = 4096
#define OF_T    4608                      // c-stride 324, e-stride 20 = 10368
#define OF_RW   14976                     // [o32][c32][18]          = 18432
#define SMEM_FLOATS 33408                 // 133632 bytes
#define T_CS 324
#define T_ES 20
#define RW_S 18

__global__ __launch_bounds__(NTHR, 1) void conv_kernel(
    const float* __restrict__ feat,
    const float* __restrict__ basis,
    const float* __restrict__ w3,
    float* __restrict__ out)
{
    extern __shared__ __align__(16) float sm[];
    const int tid = threadIdx.x;
    const int e0  = blockIdx.x * NE;

    // ---- role indices ----
    const int tg_e = tid >> 5, tg_c = tid & 31;            // T-gen
    const int a_o  = tid >> 4, a_c0 = 2 * (tid & 15);      // Phase A
    const int b_cq = tid >> 8;                             // Phase B
    const int b_og = (tid >> 4) & 15, b_e = tid & 15;
    const int b_o0 = b_og * 2, b_o1 = b_o0 + 1;

    // ---- stage H transposed: sH[m][e] ----
    { int m = tid & 31, e = tid >> 5;
      sm[OF_H + m * 16 + e] = g_H[(size_t)(e0 + e) * 32 + m]; }

    // ---- feat -> registers (16 floats for (tg_e, tg_c)) ----
    float fr[16];
    {
        const float4* fp = (const float4*)(feat + ((size_t)(e0 + tg_e) * 32 + tg_c) * 16);
        #pragma unroll
        for (int i = 0; i < 4; ++i) {
            float4 v = __ldg(fp + i);
            fr[4*i] = v.x; fr[4*i+1] = v.y; fr[4*i+2] = v.z; fr[4*i+3] = v.w;
        }
    }

    // ---- basis prefetch for f=0: thread loads 8 floats ----
    const int p_e = tid >> 5, p_d = (tid >> 1) & 15, p_h = tid & 1;
    const float* bas_base = basis + (((size_t)(e0 + p_e) * 16 + p_d) * 44) * 16 + p_h * 8;
    float4 bpre0, bpre1;
    bpre0 = __ldg((const float4*)bas_base);
    bpre1 = __ldg((const float4*)bas_base + 1);

    // ---- Phase B persistent accumulators ----
    u64 acc0[8], acc1[8];
    #pragma unroll
    for (int k = 0; k < 8; ++k) { acc0[k] = 0ull; acc1[k] = 0ull; }

    __syncthreads();   // H staged

    for (int f = 0; f < 44; ++f) {
        // stage basis slice for this f
        {
            float4* bp = (float4*)(sm + OF_BAS + tid * 8);
            bp[0] = bpre0; bp[1] = bpre1;
        }
        __syncthreads();   // sBas visible; sT/sRW safe to overwrite

        if (f < 43) {
            const float* bs = bas_base + (size_t)(f + 1) * 16;
            bpre0 = __ldg((const float4*)bs);
            bpre1 = __ldg((const float4*)bs + 1);
        }

        // ---- Phase A: issue w3 chunk-0 loads early ----
        const float* w0p = w3 + ((size_t)a_o * 1408 + (size_t)a_c0 * 44 + f) * 32;
        const float* w1p = w0p + 44 * 32;
        float4 wc[4];
        wc[0] = __ldg((const float4*)w0p);
        wc[1] = __ldg((const float4*)w0p + 1);
        wc[2] = __ldg((const float4*)w1p);
        wc[3] = __ldg((const float4*)w1p + 1);

        // ---- T-gen: T[c][e][s] = sum_d feat * bas ----
        {
            u64 t[8];
            #pragma unroll
            for (int k = 0; k < 8; ++k) t[k] = 0ull;
            const char* bb = (const char*)(sm + OF_BAS + tg_e * 256);
            #pragma unroll
            for (int d = 0; d < 16; ++d) {
                u64 fp2 = pk2(fr[d], fr[d]);
                const ulonglong2* bp = (const ulonglong2*)(bb + d * 64);
                ulonglong2 q0 = bp[0], q1 = bp[1], q2 = bp[2], q3 = bp[3];
                FMA2(t[0], fp2, q0.x, t[0]); FMA2(t[1], fp2, q0.y, t[1]);
                FMA2(t[2], fp2, q1.x, t[2]); FMA2(t[3], fp2, q1.y, t[3]);
                FMA2(t[4], fp2, q2.x, t[4]); FMA2(t[5], fp2, q2.y, t[5]);
                FMA2(t[6], fp2, q3.x, t[6]); FMA2(t[7], fp2, q3.y, t[7]);
            }
            ulonglong2* tp = (ulonglong2*)(sm + OF_T + tg_c * T_CS + tg_e * T_ES);
            #pragma unroll
            for (int k = 0; k < 4; ++k) {
                ulonglong2 v; v.x = t[2*k]; v.y = t[2*k+1];
                tp[k] = v;
            }
        }

        // ---- Phase A: rw[o][c][e] = sum_m h[m][e] * w3[o,c,f][m] ----
        {
            u64 A0[8], A1[8];
            #pragma unroll
            for (int k = 0; k < 8; ++k) { A0[k] = 0ull; A1[k] = 0ull; }

            #pragma unroll
            for (int mc = 0; mc < 4; ++mc) {
                float4 wn[4];
                if (mc < 3) {   // prefetch next chunk of 8 m
                    wn[0] = __ldg((const float4*)w0p + 2*(mc+1));
                    wn[1] = __ldg((const float4*)w0p + 2*(mc+1) + 1);
                    wn[2] = __ldg((const float4*)w1p + 2*(mc+1));
                    wn[3] = __ldg((const float4*)w1p + 2*(mc+1) + 1);
                }
                const float wv0[8] = { wc[0].x, wc[0].y, wc[0].z, wc[0].w,
                                       wc[1].x, wc[1].y, wc[1].z, wc[1].w };
                const float wv1[8] = { wc[2].x, wc[2].y, wc[2].z, wc[2].w,
                                       wc[3].x, wc[3].y, wc[3].z, wc[3].w };
                #pragma unroll
                for (int mm = 0; mm < 8; ++mm) {
                    const int m = mc * 8 + mm;
                    const ulonglong2* hp = (const ulonglong2*)(sm + OF_H + m * 16);
                    ulonglong2 h01 = hp[0], h23 = hp[1];
                    u64 wp0 = pk2(wv0[mm], wv0[mm]);
                    u64 wp1 = pk2(wv1[mm], wv1[mm]);
                    FMA2(A0[0], wp0, h01.x, A0[0]); FMA2(A0[1], wp0, h01.y, A0[1]);
                    FMA2(A0[2], wp0, h23.x, A0[2]); FMA2(A0[3], wp0, h23.y, A0[3]);
                    FMA2(A1[0], wp1, h01.x, A1[0]); FMA2(A1[1], wp1, h01.y, A1[1]);
                    FMA2(A1[2], wp1, h23.x, A1[2]); FMA2(A1[3], wp1, h23.y, A1[3]);
                    ulonglong2 h45 = hp[2], h67 = hp[3];
                    FMA2(A0[4], wp0, h45.x, A0[4]); FMA2(A0[5], wp0, h45.y, A0[5]);
                    FMA2(A0[6], wp0, h67.x, A0[6]); FMA2(A0[7], wp0, h67.y, A0[7]);
                    FMA2(A1[4], wp1, h45.x, A1[4]); FMA2(A1[5], wp1, h45.y, A1[5]);
                    FMA2(A1[6], wp1, h67.x, A1[6]); FMA2(A1[7], wp1, h67.y, A1[7]);
                }
                #pragma unroll
                for (int k = 0; k < 4; ++k) wc[k] = wn[k];
            }
            u64* rw0 = (u64*)(sm + OF_RW + ((size_t)a_o * 32 + a_c0) * RW_S);
            u64* rw1 = rw0 + RW_S / 2;   // next c row (+18 floats = +9 u64)
            #pragma unroll
            for (int k = 0; k < 8; ++k) { rw0[k] = A0[k]; rw1[k] = A1[k]; }
        }
        __syncthreads();   // sT + sRW visible

        // ---- Phase B: acc[e][o][s] += rw[o][c][e] * T[c][e][s] ----
        {
            const float* rwb0 = sm + OF_RW + (size_t)b_o0 * 32 * RW_S + b_e;
            const float* rwb1 = sm + OF_RW + (size_t)b_o1 * 32 * RW_S + b_e;
            #pragma unroll
            for (int ci = 0; ci < 16; ++ci) {
                const int c = b_cq * 16 + ci;
                const ulonglong2* tp = (const ulonglong2*)(sm + OF_T + c * T_CS + b_e * T_ES);
                ulonglong2 q0 = tp[0], q1 = tp[1], q2 = tp[2], q3 = tp[3];
                float r0 = rwb0[c * RW_S];
                float r1 = rwb1[c * RW_S];
                u64 rp0 = pk2(r0, r0);
                u64 rp1 = pk2(r1, r1);
                FMA2(acc0[0], rp0, q0.x, acc0[0]); FMA2(acc0[1], rp0, q0.y, acc0[1]);
                FMA2(acc0[2], rp0, q1.x, acc0[2]); FMA2(acc0[3], rp0, q1.y, acc0[3]);
                FMA2(acc0[4], rp0, q2.x, acc0[4]); FMA2(acc0[5], rp0, q2.y, acc0[5]);
                FMA2(acc0[6], rp0, q3.x, acc0[6]); FMA2(acc0[7], rp0, q3.y, acc0[7]);
                FMA2(acc1[0], rp1, q0.x, acc1[0]); FMA2(acc1[1], rp1, q0.y, acc1[1]);
                FMA2(acc1[2], rp1, q1.x, acc1[2]); FMA2(acc1[3], rp1, q1.y, acc1[3]);
                FMA2(acc1[4], rp1, q2.x, acc1[4]); FMA2(acc1[5], rp1, q2.y, acc1[5]);
                FMA2(acc1[6], rp1, q3.x, acc1[6]); FMA2(acc1[7], rp1, q3.y, acc1[7]);
            }
        }
    }

    // ---- reduce the two c-halves and store ----
    __syncthreads();
    if (tid >= 256) {
        u64* sp = (u64*)(sm + OF_RW) + (size_t)(tid - 256) * 16;
        #pragma unroll
        for (int k = 0; k < 8; ++k) { sp[k] = acc0[k]; sp[8 + k] = acc1[k]; }
    }
    __syncthreads();
    if (tid < 256) {
        const u64* sp = (const u64*)(sm + OF_RW) + (size_t)tid * 16;
        #pragma unroll
        for (int k = 0; k < 8; ++k) {
            u64 v0 = sp[k], v1 = sp[8 + k];
            ADD2(acc0[k], acc0[k], v0);
            ADD2(acc1[k], acc1[k], v1);
        }
        float* op0 = out + (((size_t)(e0 + b_e) * 32) + b_o0) * 16;
        float* op1 = out + (((size_t)(e0 + b_e) * 32) + b_o1) * 16;
        #pragma unroll
        for (int k = 0; k < 4; ++k) {
            ulonglong2 v;
            v.x = acc0[2*k]; v.y = acc0[2*k+1];
            ((ulonglong2*)op0)[k] = v;
            v.x = acc1[2*k]; v.y = acc1[2*k+1];
            ((ulonglong2*)op1)[k] = v;
        }
    }
}

// ---------------------------------------------------------------------------
extern "C" void kernel_launch(void* const* d_in, const int* in_sizes, int n_in,
                              void* d_out, int out_size)
{
    const float* features = (const float*)d_in[0];
    const float* inv      = (const float*)d_in[1];
    const float* basis    = (const float*)d_in[2];
    const float* w1  = (const float*)d_in[3];
    const float* b1  = (const float*)d_in[4];
    const float* g1  = (const float*)d_in[5];
    const float* be1 = (const float*)d_in[6];
    const float* w2  = (const float*)d_in[7];
    const float* b2  = (const float*)d_in[8];
    const float* g2  = (const float*)d_in[9];
    const float* be2 = (const float*)d_in[10];
    const float* w3  = (const float*)d_in[11];
    float* out = (float*)d_out;

    cudaFuncSetAttribute(conv_kernel, cudaFuncAttributeMaxDynamicSharedMemorySize,
                         SMEM_FLOATS * (int)sizeof(float));

    mlp_kernel<<<E_TOT / 8, 256>>>(inv, w1, b1, g1, be1, w2, b2, g2, be2);
    conv_kernel<<<NBLK, NTHR, SMEM_FLOATS * sizeof(float)>>>(features, basis, w3, out);
}

// round 4
// speedup vs baseline: 2.0409x; 1.0565x over previous
#include <cuda_runtime.h>
#include <cstdint>

// ============================================================================
// VersatileConvSE3: out[e,o,s] = sum_{c,f} rw[e,o,c*44+f] * T_f[e,c,s]
//   rw[e,o,cf] = sum_m h[e,m] * w3[o*1408 + c*44 + f, m]
//   T_f[e,c,s] = sum_d feat[e,c,d] * basis[e,d,f,s]
// E=16384, C=32, O=32, D=S=16, F=44, M=32
// ============================================================================

#define E_TOT   16384
#define NE      16          // edges per CTA
#define NTHR    512
#define NBLK    (E_TOT / NE)

typedef unsigned long long u64;

#define FMA2(d,a,b,c) asm("fma.rn.f32x2 %0, %1, %2, %3;" : "=l"(d) : "l"(a), "l"(b), "l"(c))
#define ADD2(d,a,b)   asm("add.rn.f32x2 %0, %1, %2;"     : "=l"(d) : "l"(a), "l"(b))

__device__ __forceinline__ u64 pk2(float a, float b) {
    u64 r; asm("mov.b64 %0, {%1, %2};" : "=l"(r) : "f"(a), "f"(b)); return r;
}

__device__ float g_H[E_TOT * 32];

// ---------------------------------------------------------------------------
// Kernel 1: radial MLP -> g_H.  One warp per edge.
// ---------------------------------------------------------------------------
__device__ __forceinline__ float warp_sum(float v) {
    v += __shfl_xor_sync(0xffffffffu, v, 16);
    v += __shfl_xor_sync(0xffffffffu, v, 8);
    v += __shfl_xor_sync(0xffffffffu, v, 4);
    v += __shfl_xor_sync(0xffffffffu, v, 2);
    v += __shfl_xor_sync(0xffffffffu, v, 1);
    return v;
}

__global__ __launch_bounds__(256) void mlp_kernel(
    const float* __restrict__ inv,
    const float* __restrict__ w1, const float* __restrict__ b1,
    const float* __restrict__ g1, const float* __restrict__ be1,
    const float* __restrict__ w2, const float* __restrict__ b2,
    const float* __restrict__ g2, const float* __restrict__ be2)
{
    const int e    = blockIdx.x * 8 + (threadIdx.x >> 5);
    const int lane = threadIdx.x & 31;
    const float* x = inv + e * 16;

    float y = b1[lane];
    #pragma unroll
    for (int d = 0; d < 16; ++d) y += x[d] * w1[lane * 16 + d];

    float mu  = warp_sum(y) * (1.0f / 32.0f);
    float dz  = y - mu;
    float var = warp_sum(dz * dz) * (1.0f / 32.0f);
    float rs  = rsqrtf(var + 1e-5f);
    float h1  = fmaxf(dz * rs * g1[lane] + be1[lane], 0.0f);

    float y2 = b2[lane];
    #pragma unroll
    for (int m = 0; m < 32; ++m)
        y2 += __shfl_sync(0xffffffffu, h1, m) * w2[lane * 32 + m];

    mu  = warp_sum(y2) * (1.0f / 32.0f);
    dz  = y2 - mu;
    var = warp_sum(dz * dz) * (1.0f / 32.0f);
    rs  = rsqrtf(var + 1e-5f);
    g_H[e * 32 + lane] = fmaxf(dz * rs * g2[lane] + be2[lane], 0.0f);
}

// ---------------------------------------------------------------------------
// Kernel 2: fused conv. 16 edges per CTA, 512 threads.
// Per f:
//   T-gen : thread (e=tid>>5, c=tid&31) builds T[c][e][16s] (bas broadcast LDS)
//   PhaseA: thread (o=tid>>4, c0=2*(tid&15)) computes rw[o][c0..c0+1][16e]
//           w3 -> registers (LDG, single consumer), h -> broadcast LDS.128
//   PhaseB: thread (cq=tid>>8, og=(tid>>4)&15, e=tid&15) accumulates
//           out[e][2o][16s] over its c-half (persistent registers, reduce at end)
// ---------------------------------------------------------------------------
// smem float offsets (all 16B aligned)
#define OF_H    0                         // [m32][e16]              = 512
#define OF_BAS  512                       // [e16][d16][s16]         = 4096
#define OF_T    4608                      // c-stride 324, e-stride 20 = 10368
#define OF_RW   14976                     // [o32][c32][18]          = 18432
#define SMEM_FLOATS 33408                 // 133632 bytes
#define T_CS 324
#define T_ES 20
#define RW_S 18

__global__ __launch_bounds__(NTHR, 1) void conv_kernel(
    const float* __restrict__ feat,
    const float* __restrict__ basis,
    const float* __restrict__ w3,
    float* __restrict__ out)
{
    extern __shared__ __align__(16) float sm[];
    const int tid = threadIdx.x;
    const int e0  = blockIdx.x * NE;

    // ---- role indices ----
    const int tg_e = tid >> 5, tg_c = tid & 31;            // T-gen
    const int a_o  = tid >> 4, a_c0 = 2 * (tid & 15);      // Phase A
    const int b_cq = tid >> 8;                             // Phase B
    const int b_og = (tid >> 4) & 15, b_e = tid & 15;
    const int b_o0 = b_og * 2, b_o1 = b_o0 + 1;

    // ---- stage H transposed: sH[m][e] ----
    { int m = tid & 31, e = tid >> 5;
      sm[OF_H + m * 16 + e] = g_H[(size_t)(e0 + e) * 32 + m]; }

    // ---- feat -> registers (16 floats for (tg_e, tg_c)) ----
    float fr[16];
    {
        const float4* fp = (const float4*)(feat + ((size_t)(e0 + tg_e) * 32 + tg_c) * 16);
        #pragma unroll
        for (int i = 0; i < 4; ++i) {
            float4 v = __ldg(fp + i);
            fr[4*i] = v.x; fr[4*i+1] = v.y; fr[4*i+2] = v.z; fr[4*i+3] = v.w;
        }
    }

    // ---- basis prefetch for f=0: thread loads 8 floats ----
    const int p_e = tid >> 5, p_d = (tid >> 1) & 15, p_h = tid & 1;
    const float* bas_base = basis + (((size_t)(e0 + p_e) * 16 + p_d) * 44) * 16 + p_h * 8;
    float4 bpre0, bpre1;
    bpre0 = __ldg((const float4*)bas_base);
    bpre1 = __ldg((const float4*)bas_base + 1);

    // ---- Phase B persistent accumulators ----
    u64 acc0[8], acc1[8];
    #pragma unroll
    for (int k = 0; k < 8; ++k) { acc0[k] = 0ull; acc1[k] = 0ull; }

    __syncthreads();   // H staged

    for (int f = 0; f < 44; ++f) {
        // stage basis slice for this f
        {
            float4* bp = (float4*)(sm + OF_BAS + tid * 8);
            bp[0] = bpre0; bp[1] = bpre1;
        }
        __syncthreads();   // sBas visible; sT/sRW safe to overwrite

        if (f < 43) {
            const float* bs = bas_base + (size_t)(f + 1) * 16;
            bpre0 = __ldg((const float4*)bs);
            bpre1 = __ldg((const float4*)bs + 1);
        }

        // ---- Phase A: issue w3 chunk-0 loads early ----
        const float* w0p = w3 + ((size_t)a_o * 1408 + (size_t)a_c0 * 44 + f) * 32;
        const float* w1p = w0p + 44 * 32;
        float4 wc[4];
        wc[0] = __ldg((const float4*)w0p);
        wc[1] = __ldg((const float4*)w0p + 1);
        wc[2] = __ldg((const float4*)w1p);
        wc[3] = __ldg((const float4*)w1p + 1);

        // ---- T-gen: T[c][e][s] = sum_d feat * bas ----
        {
            u64 t[8];
            #pragma unroll
            for (int k = 0; k < 8; ++k) t[k] = 0ull;
            const char* bb = (const char*)(sm + OF_BAS + tg_e * 256);
            #pragma unroll
            for (int d = 0; d < 16; ++d) {
                u64 fp2 = pk2(fr[d], fr[d]);
                const ulonglong2* bp = (const ulonglong2*)(bb + d * 64);
                ulonglong2 q0 = bp[0], q1 = bp[1], q2 = bp[2], q3 = bp[3];
                FMA2(t[0], fp2, q0.x, t[0]); FMA2(t[1], fp2, q0.y, t[1]);
                FMA2(t[2], fp2, q1.x, t[2]); FMA2(t[3], fp2, q1.y, t[3]);
                FMA2(t[4], fp2, q2.x, t[4]); FMA2(t[5], fp2, q2.y, t[5]);
                FMA2(t[6], fp2, q3.x, t[6]); FMA2(t[7], fp2, q3.y, t[7]);
            }
            ulonglong2* tp = (ulonglong2*)(sm + OF_T + tg_c * T_CS + tg_e * T_ES);
            #pragma unroll
            for (int k = 0; k < 4; ++k) {
                ulonglong2 v; v.x = t[2*k]; v.y = t[2*k+1];
                tp[k] = v;
            }
        }

        // ---- Phase A: rw[o][c][e] = sum_m h[m][e] * w3[o,c,f][m] ----
        {
            u64 A0[8], A1[8];
            #pragma unroll
            for (int k = 0; k < 8; ++k) { A0[k] = 0ull; A1[k] = 0ull; }

            #pragma unroll
            for (int mc = 0; mc < 4; ++mc) {
                float4 wn[4];
                if (mc < 3) {   // prefetch next chunk of 8 m
                    wn[0] = __ldg((const float4*)w0p + 2*(mc+1));
                    wn[1] = __ldg((const float4*)w0p + 2*(mc+1) + 1);
                    wn[2] = __ldg((const float4*)w1p + 2*(mc+1));
                    wn[3] = __ldg((const float4*)w1p + 2*(mc+1) + 1);
                }
                const float wv0[8] = { wc[0].x, wc[0].y, wc[0].z, wc[0].w,
                                       wc[1].x, wc[1].y, wc[1].z, wc[1].w };
                const float wv1[8] = { wc[2].x, wc[2].y, wc[2].z, wc[2].w,
                                       wc[3].x, wc[3].y, wc[3].z, wc[3].w };
                #pragma unroll
                for (int mm = 0; mm < 8; ++mm) {
                    const int m = mc * 8 + mm;
                    const ulonglong2* hp = (const ulonglong2*)(sm + OF_H + m * 16);
                    ulonglong2 h01 = hp[0], h23 = hp[1];
                    u64 wp0 = pk2(wv0[mm], wv0[mm]);
                    u64 wp1 = pk2(wv1[mm], wv1[mm]);
                    FMA2(A0[0], wp0, h01.x, A0[0]); FMA2(A0[1], wp0, h01.y, A0[1]);
                    FMA2(A0[2], wp0, h23.x, A0[2]); FMA2(A0[3], wp0, h23.y, A0[3]);
                    FMA2(A1[0], wp1, h01.x, A1[0]); FMA2(A1[1], wp1, h01.y, A1[1]);
                    FMA2(A1[2], wp1, h23.x, A1[2]); FMA2(A1[3], wp1, h23.y, A1[3]);
                    ulonglong2 h45 = hp[2], h67 = hp[3];
                    FMA2(A0[4], wp0, h45.x, A0[4]); FMA2(A0[5], wp0, h45.y, A0[5]);
                    FMA2(A0[6], wp0, h67.x, A0[6]); FMA2(A0[7], wp0, h67.y, A0[7]);
                    FMA2(A1[4], wp1, h45.x, A1[4]); FMA2(A1[5], wp1, h45.y, A1[5]);
                    FMA2(A1[6], wp1, h67.x, A1[6]); FMA2(A1[7], wp1, h67.y, A1[7]);
                }
                #pragma unroll
                for (int k = 0; k < 4; ++k) wc[k] = wn[k];
            }
            u64* rw0 = (u64*)(sm + OF_RW + ((size_t)a_o * 32 + a_c0) * RW_S);
            u64* rw1 = rw0 + RW_S / 2;   // next c row (+18 floats = +9 u64)
            #pragma unroll
            for (int k = 0; k < 8; ++k) { rw0[k] = A0[k]; rw1[k] = A1[k]; }
        }
        __syncthreads();   // sT + sRW visible

        // ---- Phase B: acc[e][o][s] += rw[o][c][e] * T[c][e][s] ----
        {
            const float* rwb0 = sm + OF_RW + (size_t)b_o0 * 32 * RW_S + b_e;
            const float* rwb1 = sm + OF_RW + (size_t)b_o1 * 32 * RW_S + b_e;
            #pragma unroll
            for (int ci = 0; ci < 16; ++ci) {
                const int c = b_cq * 16 + ci;
                const ulonglong2* tp = (const ulonglong2*)(sm + OF_T + c * T_CS + b_e * T_ES);
                ulonglong2 q0 = tp[0], q1 = tp[1], q2 = tp[2], q3 = tp[3];
                float r0 = rwb0[c * RW_S];
                float r1 = rwb1[c * RW_S];
                u64 rp0 = pk2(r0, r0);
                u64 rp1 = pk2(r1, r1);
                FMA2(acc0[0], rp0, q0.x, acc0[0]); FMA2(acc0[1], rp0, q0.y, acc0[1]);
                FMA2(acc0[2], rp0, q1.x, acc0[2]); FMA2(acc0[3], rp0, q1.y, acc0[3]);
                FMA2(acc0[4], rp0, q2.x, acc0[4]); FMA2(acc0[5], rp0, q2.y, acc0[5]);
                FMA2(acc0[6], rp0, q3.x, acc0[6]); FMA2(acc0[7], rp0, q3.y, acc0[7]);
                FMA2(acc1[0], rp1, q0.x, acc1[0]); FMA2(acc1[1], rp1, q0.y, acc1[1]);
                FMA2(acc1[2], rp1, q1.x, acc1[2]); FMA2(acc1[3], rp1, q1.y, acc1[3]);
                FMA2(acc1[4], rp1, q2.x, acc1[4]); FMA2(acc1[5], rp1, q2.y, acc1[5]);
                FMA2(acc1[6], rp1, q3.x, acc1[6]); FMA2(acc1[7], rp1, q3.y, acc1[7]);
            }
        }
    }

    // ---- reduce the two c-halves and store ----
    __syncthreads();
    if (tid >= 256) {
        u64* sp = (u64*)(sm + OF_RW) + (size_t)(tid - 256) * 16;
        #pragma unroll
        for (int k = 0; k < 8; ++k) { sp[k] = acc0[k]; sp[8 + k] = acc1[k]; }
    }
    __syncthreads();
    if (tid < 256) {
        const u64* sp = (const u64*)(sm + OF_RW) + (size_t)tid * 16;
        #pragma unroll
        for (int k = 0; k < 8; ++k) {
            u64 v0 = sp[k], v1 = sp[8 + k];
            ADD2(acc0[k], acc0[k], v0);
            ADD2(acc1[k], acc1[k], v1);
        }
        float* op0 = out + (((size_t)(e0 + b_e) * 32) + b_o0) * 16;
        float* op1 = out + (((size_t)(e0 + b_e) * 32) + b_o1) * 16;
        #pragma unroll
        for (int k = 0; k < 4; ++k) {
            ulonglong2 v;
            v.x = acc0[2*k]; v.y = acc0[2*k+1];
            ((ulonglong2*)op0)[k] = v;
            v.x = acc1[2*k]; v.y = acc1[2*k+1];
            ((ulonglong2*)op1)[k] = v;
        }
    }
}

// ---------------------------------------------------------------------------
extern "C" void kernel_launch(void* const* d_in, const int* in_sizes, int n_in,
                              void* d_out, int out_size)
{
    const float* features = (const float*)d_in[0];
    const float* inv      = (const float*)d_in[1];
    const float* basis    = (const float*)d_in[2];
    const float* w1  = (const float*)d_in[3];
    const float* b1  = (const float*)d_in[4];
    const float* g1  = (const float*)d_in[5];
    const float* be1 = (const float*)d_in[6];
    const float* w2  = (const float*)d_in[7];
    const float* b2  = (const float*)d_in[8];
    const float* g2  = (const float*)d_in[9];
    const float* be2 = (const float*)d_in[10];
    const float* w3  = (const float*)d_in[11];
    float* out = (float*)d_out;

    cudaFuncSetAttribute(conv_kernel, cudaFuncAttributeMaxDynamicSharedMemorySize,
                         SMEM_FLOATS * (int)sizeof(float));

    mlp_kernel<<<E_TOT / 8, 256>>>(inv, w1, b1, g1, be1, w2, b2, g2, be2);
    conv_kernel<<<NBLK, NTHR, SMEM_FLOATS * sizeof(float)>>>(features, basis, w3, out);
}